// round 8
// baseline (speedup 1.0000x reference)
#include <cuda_runtime.h>
#include <cstdint>

#define DEV_INLINE __device__ __forceinline__

// ------------- device-global scratch -------------
static __device__ float g_G[2ULL * 512 * 64 * 2048];    // gate preactivations [d][T][B][4H]
static __device__ float g_h1[512 * 64 * 1024];          // layer-0 output [T][B][2H]
static __device__ float g_h2[512 * 64 * 1024];          // layer-1 output
static __device__ float g_xr[64 * 512 * 168];           // tf32-rounded x
static __device__ float g_w0r[2 * 2048 * 168];
static __device__ float g_w1r[2 * 2048 * 1024];
static __device__ float g_wor[168 * 1024];
static __device__ float g_hbuf[2][2][2][64][512];       // [layer][dir][parity][b][k]
static __device__ int   g_bar[8][256];                  // [layer*4+d*2+bh][cta*8] flags

// ------------- helpers -------------
DEV_INLINE unsigned sptr(const void* p) { return (unsigned)__cvta_generic_to_shared(p); }

DEV_INLINE void cp16(void* d, const void* s, int bytes) {
    asm volatile("cp.async.cg.shared.global [%0],[%1],16,%2;\n"
                 :: "r"(sptr(d)), "l"(s), "r"(bytes));
}
DEV_INLINE void cp_commit() { asm volatile("cp.async.commit_group;\n"); }
DEV_INLINE void cp_wait0()  { asm volatile("cp.async.wait_group 0;\n"); }
DEV_INLINE void cp_wait2()  { asm volatile("cp.async.wait_group 2;\n"); }

DEV_INLINE float tf32r(float x) {
    unsigned r;
    asm("cvt.rna.tf32.f32 %0, %1;" : "=r"(r) : "f"(x));
    return __uint_as_float(r);
}

DEV_INLINE void mma8(float c[4], const unsigned a[4], const unsigned b[2]) {
    asm volatile("mma.sync.aligned.m16n8k8.row.col.f32.tf32.tf32.f32 "
                 "{%0,%1,%2,%3},{%4,%5,%6,%7},{%8,%9},{%0,%1,%2,%3};"
                 : "+f"(c[0]), "+f"(c[1]), "+f"(c[2]), "+f"(c[3])
                 : "r"(a[0]), "r"(a[1]), "r"(a[2]), "r"(a[3]),
                   "r"(b[0]), "r"(b[1]));
}

DEV_INLINE int ld_acq(const int* p) {
    int v;
    asm volatile("ld.acquire.gpu.global.b32 %0,[%1];" : "=r"(v) : "l"(p) : "memory");
    return v;
}
DEV_INLINE void st_rel(int* p, int v) {
    asm volatile("st.release.gpu.global.b32 [%0],%1;" :: "l"(p), "r"(v) : "memory");
}

DEV_INLINE float sigm(float x)   { return 1.0f / (1.0f + __expf(-x)); }
DEV_INLINE float tanh_f(float x) { float e = __expf(2.0f * x); return 1.0f - 2.0f / (e + 1.0f); }

// ------------- tf32 pre-rounding -------------
__global__ void round_all_k(const float* __restrict__ x,  const float* __restrict__ w0,
                            const float* __restrict__ w1, const float* __restrict__ wo) {
    const int N0 = 64 * 512 * 168;
    const int N1 = 2 * 2048 * 168;
    const int N2 = 2 * 2048 * 1024;
    const int N3 = 168 * 1024;
    int total = N0 + N1 + N2 + N3;
    for (int i = blockIdx.x * blockDim.x + threadIdx.x; i < total; i += gridDim.x * blockDim.x) {
        if (i < N0)                 g_xr[i] = tf32r(x[i]);
        else if (i < N0 + N1)       g_w0r[i - N0] = tf32r(w0[i - N0]);
        else if (i < N0 + N1 + N2)  g_w1r[i - N0 - N1] = tf32r(w1[i - N0 - N1]);
        else                        g_wor[i - N0 - N1 - N2] = tf32r(wo[i - N0 - N1 - N2]);
    }
}

__global__ void reset_k() {
    int gt = blockIdx.x * 256 + threadIdx.x;
    if (gt < 8 * 256) ((int*)g_bar)[gt] = 0;
    float* hb = &g_hbuf[0][0][0][0][0];
    for (int i = gt; i < 2 * 2 * 2 * 64 * 512; i += 64 * 256) hb[i] = 0.0f;
}

// ------------- tf32 GEMM, 4-stage cp.async pipeline -------------
// tile 128(M) x 64(N), k-tile 16, 256 threads (warps 4m x 2n, each m32 x n32)
// out offset = (m/DIV)*S1 + (m%DIV)*S2 + (n>>11)*S3 + (n&2047)
__global__ void __launch_bounds__(256, 2)
gemm_k(const float* __restrict__ A, const float* __restrict__ W,
       const float* __restrict__ bias, float* __restrict__ C,
       int M, int N, int K, int DIV, long long S1, long long S2, long long S3) {
    extern __shared__ float gsm[];
    float* Asm = gsm;                 // 4 x 128 x 20
    float* Bsm = gsm + 4 * 2560;      // 4 x  64 x 20

    int tid = threadIdx.x, lane = tid & 31, wid = tid >> 5;
    int wm = wid & 3, wn = wid >> 2;
    int mbase = blockIdx.y * 128, nbase = blockIdx.x * 64;
    int KT = (K + 15) >> 4;

    float acc[2][4][4];
#pragma unroll
    for (int mt = 0; mt < 2; mt++)
#pragma unroll
        for (int nt = 0; nt < 4; nt++)
#pragma unroll
            for (int e = 0; e < 4; e++) acc[mt][nt][e] = 0.0f;

    auto load_stage = [&](int kt) {
        int s = kt & 3;
        int k0 = kt * 16;
        float* as = Asm + s * 2560;
        float* bs = Bsm + s * 1280;
#pragma unroll
        for (int i = 0; i < 2; i++) {
            int ch = i * 256 + tid;
            int row = ch >> 2, seg = ch & 3;
            int k = k0 + seg * 4;
            int el = K - k; if (el > 4) el = 4; if (el < 0) el = 0;
            int bytes = el * 4;
            const float* src = A + (size_t)(mbase + row) * K + (bytes ? k : 0);
            cp16(&as[row * 20 + seg * 4], src, bytes);
        }
        {
            int row = tid >> 2, seg = tid & 3;
            int k = k0 + seg * 4;
            int n = nbase + row;
            int el = K - k; if (el > 4) el = 4; if (el < 0) el = 0;
            int bytes = el * 4;
            if (n >= N) bytes = 0;
            const float* src = (bytes ? (W + (size_t)n * K + k) : W);
            cp16(&bs[row * 20 + seg * 4], src, bytes);
        }
        cp_commit();
    };

    load_stage(0);
    if (KT > 1) load_stage(1);
    if (KT > 2) load_stage(2);

    for (int kt = 0; kt < KT; kt++) {
        cp_wait2();
        __syncthreads();
        if (kt + 3 < KT) load_stage(kt + 3);
        const float* as = Asm + (kt & 3) * 2560;
        const float* bs = Bsm + (kt & 3) * 1280;
#pragma unroll
        for (int k8 = 0; k8 < 2; k8++) {
            int kk = k8 * 8 + (lane & 3);
            unsigned a[2][4], b[4][2];
#pragma unroll
            for (int mt = 0; mt < 2; mt++) {
                int r0 = wm * 32 + mt * 16 + (lane >> 2);
                a[mt][0] = __float_as_uint(as[r0 * 20 + kk]);
                a[mt][1] = __float_as_uint(as[(r0 + 8) * 20 + kk]);
                a[mt][2] = __float_as_uint(as[r0 * 20 + kk + 4]);
                a[mt][3] = __float_as_uint(as[(r0 + 8) * 20 + kk + 4]);
            }
#pragma unroll
            for (int nt = 0; nt < 4; nt++) {
                int c0 = wn * 32 + nt * 8 + (lane >> 2);
                b[nt][0] = __float_as_uint(bs[c0 * 20 + kk]);
                b[nt][1] = __float_as_uint(bs[c0 * 20 + kk + 4]);
            }
#pragma unroll
            for (int mt = 0; mt < 2; mt++)
#pragma unroll
                for (int nt = 0; nt < 4; nt++)
                    mma8(acc[mt][nt], a[mt], b[nt]);
        }
    }

#pragma unroll
    for (int mt = 0; mt < 2; mt++) {
#pragma unroll
        for (int nt = 0; nt < 4; nt++) {
            int m0 = mbase + wm * 32 + mt * 16 + (lane >> 2);
            int n0 = nbase + wn * 32 + nt * 8 + 2 * (lane & 3);
            if (n0 < N) {
                float bv0 = bias[n0], bv1 = bias[n0 + 1];
                long long nb = (long long)(n0 >> 11) * S3 + (n0 & 2047);
                long long o0 = (long long)(m0 / DIV) * S1 + (long long)(m0 % DIV) * S2 + nb;
                int m1 = m0 + 8;
                long long o1 = (long long)(m1 / DIV) * S1 + (long long)(m1 % DIV) * S2 + nb;
                *(float2*)(C + o0) = make_float2(acc[mt][nt][0] + bv0, acc[mt][nt][1] + bv1);
                *(float2*)(C + o1) = make_float2(acc[mt][nt][2] + bv0, acc[mt][nt][3] + bv1);
            }
        }
    }
}

// ------------- persistent bidirectional LSTM recurrence, 2-D split -------------
// grid 128: d = bx>>6, bh = (bx>>5)&1, ncta = bx&31.
// CTA owns batches [bh*32, bh*32+32) x hidden units [ncta*16, ncta*16+16).
// Per-chunk dataflow: chunk c only needs flags of producer CTAs 4c..4c+3.
__global__ void __launch_bounds__(128, 1)
lstm_k(const float* __restrict__ Whh, const float* __restrict__ G,
       float* __restrict__ hout, int layer) {
    extern __shared__ float sm[];
    float* bf  = sm;                            // W frags [wn4][c8][k8 8][lane32][4] = 32768
    float* hs  = sm + 32768;                    // h: 4 bufs x (32 x 68) = 8704
    float* Gs  = sm + 32768 + 8704;             // 32 x 64 = 2048
    float* dmp = sm + 32768 + 8704 + 2048;      // 32 x 68 = 2176

    const int tid = threadIdx.x;
    const int lane = tid & 31, wn = tid >> 5;   // 4 n-warps
    const int d = blockIdx.x >> 6;
    const int bh = (blockIdx.x >> 5) & 1;
    const int ncta = blockIdx.x & 31;
    const int jbase = ncta * 16;
    int* bar = &g_bar[layer * 4 + d * 2 + bh][0];

    // ---- preload Whh slice (64 rows x 512) into fragment-ordered SMEM ----
    const float* Wd = Whh + (size_t)d * 2048 * 512;
    for (int idx = tid; idx < 64 * 512; idx += 128) {
        int ns = idx >> 9, k = idx & 511;
        int grow = (ns & 3) * 512 + jbase + (ns >> 2);   // gate*512 + unit
        float v = tf32r(Wd[(size_t)grow * 512 + k]);
        int wnn = ns >> 4;               // owning warp
        int r = ns & 15;                 // row within warp tile
        int nt = r >> 3;
        int c = k >> 6, k8 = (k >> 3) & 7;
        int ln = ((r & 7) << 2) | (k & 3);
        int elem = nt * 2 + ((k >> 2) & 1);
        bf[(((wnn * 8 + c) * 8 + k8) * 32 + ln) * 4 + elem] = v;
    }
    __syncthreads();

    const float* Gbase = G + (size_t)d * 512 * 64 * 2048;
    float cst[4];
#pragma unroll
    for (int i = 0; i < 4; i++) cst[i] = 0.0f;
    const int b_ep = tid >> 2;           // local batch 0..31
    const int uoff = (tid & 3) * 4;      // unit group 0,4,8,12

    for (int t = 0; t < 512; t++) {
        int tt = d ? (511 - t) : t;

        // stage gate preactivations (no dependency on other CTAs)
        const float* Gp = Gbase + (size_t)tt * 64 * 2048 + (size_t)(bh * 32) * 2048;
#pragma unroll
        for (int i = 0; i < 4; i++) {
            int s = tid * 4 + i;                  // 0..511
            int b = s >> 4, g = (s >> 2) & 3, part = s & 3;
            cp16(Gs + b * 64 + g * 16 + part * 4,
                 Gp + (size_t)b * 2048 + g * 512 + jbase + part * 4, 16);
        }
        cp_commit();

        const float* hsrc = &g_hbuf[layer][d][(t + 1) & 1][bh * 32][0];

        // per-chunk producer wait: chunk c needs CTAs 4c..4c+3 done with step t-1
        auto pollchunk = [&](int c) {
            const int f = 4 * c * 8;
            for (;;) {
                int a0 = ld_acq(&bar[f]);
                int a1 = ld_acq(&bar[f + 8]);
                int a2 = ld_acq(&bar[f + 16]);
                int a3 = ld_acq(&bar[f + 24]);
                if (a0 >= t && a1 >= t && a2 >= t && a3 >= t) break;
            }
        };

        // stage one 64-wide k-chunk of h for 32 batches (2048 floats, 4 cp16/thr)
        auto stage = [&](int c) {
            float* dst = hs + (c & 3) * 2176;
            const float* src = hsrc + c * 64;
#pragma unroll
            for (int i = 0; i < 4; i++) {
                int s = tid * 4 + i;              // 0..511
                int b = s >> 4, kp = (s & 15) * 4;
                cp16(dst + b * 68 + kp, src + b * 512 + kp, 16);
            }
            cp_commit();
        };
        pollchunk(0); stage(0);
        pollchunk(1); stage(1);
        pollchunk(2); stage(2);

        float acc[2][2][4];
#pragma unroll
        for (int mt = 0; mt < 2; mt++)
#pragma unroll
            for (int nt = 0; nt < 2; nt++)
#pragma unroll
                for (int e = 0; e < 4; e++) acc[mt][nt][e] = 0.0f;

#pragma unroll
        for (int c = 0; c < 8; c++) {
            if (c < 6) cp_wait2(); else cp_wait0();
            __syncthreads();
            if (c < 5) { pollchunk(c + 3); stage(c + 3); }

            const float* hc = hs + (c & 3) * 2176;
            const float* Bb = bf + ((wn * 8 + c) * 8) * 128;
#pragma unroll
            for (int k8 = 0; k8 < 8; k8++) {
                int kk = k8 * 8 + (lane & 3);
                int r0 = lane >> 2;
                unsigned a[2][4], bb[2][2];
#pragma unroll
                for (int mt = 0; mt < 2; mt++) {
                    int r = r0 + mt * 16;
                    a[mt][0] = __float_as_uint(hc[r * 68 + kk]);
                    a[mt][1] = __float_as_uint(hc[(r + 8) * 68 + kk]);
                    a[mt][2] = __float_as_uint(hc[r * 68 + kk + 4]);
                    a[mt][3] = __float_as_uint(hc[(r + 8) * 68 + kk + 4]);
                }
                float4 bv = *(const float4*)(Bb + (k8 * 32 + lane) * 4);
                bb[0][0] = __float_as_uint(bv.x); bb[0][1] = __float_as_uint(bv.y);
                bb[1][0] = __float_as_uint(bv.z); bb[1][1] = __float_as_uint(bv.w);
#pragma unroll
                for (int mt = 0; mt < 2; mt++)
#pragma unroll
                    for (int nt = 0; nt < 2; nt++)
                        mma8(acc[mt][nt], a[mt], bb[nt]);
            }
        }

        // dump gates to SMEM for the cross-thread transpose (m 0..31, n 0..63)
#pragma unroll
        for (int mt = 0; mt < 2; mt++) {
#pragma unroll
            for (int nt = 0; nt < 2; nt++) {
                int m0 = mt * 16 + (lane >> 2);
                int n0 = wn * 16 + nt * 8 + 2 * (lane & 3);
                dmp[m0 * 68 + n0]           = acc[mt][nt][0];
                dmp[m0 * 68 + n0 + 1]       = acc[mt][nt][1];
                dmp[(m0 + 8) * 68 + n0]     = acc[mt][nt][2];
                dmp[(m0 + 8) * 68 + n0 + 1] = acc[mt][nt][3];
            }
        }
        __syncthreads();

        // epilogue: thread handles local batch b_ep, units uoff..uoff+3
        float hr[4];
#pragma unroll
        for (int i = 0; i < 4; i++) {
            int u = uoff + i;
            float gi = dmp[b_ep * 68 + u * 4 + 0] + Gs[b_ep * 64 + 0 * 16 + u];
            float gf = dmp[b_ep * 68 + u * 4 + 1] + Gs[b_ep * 64 + 1 * 16 + u];
            float gg = dmp[b_ep * 68 + u * 4 + 2] + Gs[b_ep * 64 + 2 * 16 + u];
            float go = dmp[b_ep * 68 + u * 4 + 3] + Gs[b_ep * 64 + 3 * 16 + u];
            float cv = sigm(gf) * cst[i] + sigm(gi) * tanh_f(gg);
            cst[i] = cv;
            hr[i] = tf32r(sigm(go) * tanh_f(cv));
        }

        int bglob = bh * 32 + b_ep;
        float* hb = &g_hbuf[layer][d][t & 1][bglob][jbase + uoff];
        *(float4*)hb = make_float4(hr[0], hr[1], hr[2], hr[3]);
        float* ho = hout + ((size_t)tt * 64 + bglob) * 1024 + d * 512 + jbase + uoff;
        *(float4*)ho = make_float4(hr[0], hr[1], hr[2], hr[3]);

        __syncthreads();   // Gs/dmp/hs WAR protection + order stores before release
        if (tid == 0 && t < 511) st_rel(&bar[ncta * 8], t + 1);
    }
}

// ------------- host launcher -------------
extern "C" void kernel_launch(void* const* d_in, const int* in_sizes, int n_in,
                              void* d_out, int out_size) {
    (void)in_sizes; (void)n_in; (void)out_size;
    const float* Whh0 = (const float*)d_in[2];
    const float* b0   = (const float*)d_in[3];
    const float* Whh1 = (const float*)d_in[5];
    const float* b1   = (const float*)d_in[6];
    const float* bout = (const float*)d_in[8];
    float* out = (float*)d_out;

    const int LSMEM = (32768 + 8704 + 2048 + 2176) * 4;   // 182784
    const int GSMEM = (4 * 2560 + 4 * 1280) * 4;          // 61440
    cudaFuncSetAttribute(lstm_k, cudaFuncAttributeMaxDynamicSharedMemorySize, LSMEM);
    cudaFuncSetAttribute(gemm_k, cudaFuncAttributeMaxDynamicSharedMemorySize, GSMEM);

    float *xr, *w0r, *w1r, *wor, *G, *h1, *h2;
    cudaGetSymbolAddress((void**)&xr,  g_xr);
    cudaGetSymbolAddress((void**)&w0r, g_w0r);
    cudaGetSymbolAddress((void**)&w1r, g_w1r);
    cudaGetSymbolAddress((void**)&wor, g_wor);
    cudaGetSymbolAddress((void**)&G,   g_G);
    cudaGetSymbolAddress((void**)&h1,  g_h1);
    cudaGetSymbolAddress((void**)&h2,  g_h2);

    const long long GSZ = 512LL * 64 * 2048;

    // launch order chosen so lstm_k (layer 0) is the 4th launch == profiled slot
    reset_k<<<64, 256>>>();
    round_all_k<<<2048, 256>>>((const float*)d_in[0], (const float*)d_in[1],
                               (const float*)d_in[4], (const float*)d_in[7]);

    // layer-0 input GEMM, both directions fused on N (N=4096, K=168)
    gemm_k<<<dim3(64, 256), 256, GSMEM>>>(xr, w0r, b0, G,
                                          32768, 4096, 168, 512, 2048LL, 131072LL, GSZ);
    lstm_k<<<128, 128, LSMEM>>>(Whh0, G, h1, 0);

    // layer-1 input GEMM (N=4096, K=1024)
    gemm_k<<<dim3(64, 256), 256, GSMEM>>>(h1, w1r, b1, G,
                                          32768, 4096, 1024, 64, 131072LL, 2048LL, GSZ);
    lstm_k<<<128, 128, LSMEM>>>(Whh1, G, h2, 1);

    // output projection
    gemm_k<<<dim3(3, 256), 256, GSMEM>>>(h2, wor, bout, out,
                                         32768, 168, 1024, 64, 168LL, 86016LL, 0LL);
}

// round 9
// speedup vs baseline: 1.4839x; 1.4839x over previous
#include <cuda_runtime.h>
#include <cstdint>

#define DEV_INLINE __device__ __forceinline__

// ------------- device-global scratch -------------
static __device__ float g_G[2ULL * 512 * 64 * 2048];    // gate preactivations [d][T][B][4H]
static __device__ float g_h1[512 * 64 * 1024];          // layer-0 output [T][B][2H]
static __device__ float g_h2[512 * 64 * 1024];          // layer-1 output
static __device__ float g_xr[64 * 512 * 168];           // tf32-rounded x
static __device__ float g_w0r[2 * 2048 * 168];
static __device__ float g_w1r[2 * 2048 * 1024];
static __device__ float g_wor[168 * 1024];
static __device__ float g_hbuf[2][2][2][64][512];       // [layer][dir][parity][b][k]
static __device__ int   g_bar[8][256];                  // [layer*4+d*2+bh][cta*8] flags

// ------------- helpers -------------
DEV_INLINE unsigned sptr(const void* p) { return (unsigned)__cvta_generic_to_shared(p); }

DEV_INLINE void cp16(void* d, const void* s, int bytes) {
    asm volatile("cp.async.cg.shared.global [%0],[%1],16,%2;\n"
                 :: "r"(sptr(d)), "l"(s), "r"(bytes));
}
DEV_INLINE void cp_commit() { asm volatile("cp.async.commit_group;\n"); }
DEV_INLINE void cp_wait0()  { asm volatile("cp.async.wait_group 0;\n"); }
DEV_INLINE void cp_wait2()  { asm volatile("cp.async.wait_group 2;\n"); }

DEV_INLINE float tf32r(float x) {
    unsigned r;
    asm("cvt.rna.tf32.f32 %0, %1;" : "=r"(r) : "f"(x));
    return __uint_as_float(r);
}

DEV_INLINE void mma8(float c[4], const unsigned a[4], const unsigned b[2]) {
    asm volatile("mma.sync.aligned.m16n8k8.row.col.f32.tf32.tf32.f32 "
                 "{%0,%1,%2,%3},{%4,%5,%6,%7},{%8,%9},{%0,%1,%2,%3};"
                 : "+f"(c[0]), "+f"(c[1]), "+f"(c[2]), "+f"(c[3])
                 : "r"(a[0]), "r"(a[1]), "r"(a[2]), "r"(a[3]),
                   "r"(b[0]), "r"(b[1]));
}

DEV_INLINE int ld_acq(const int* p) {
    int v;
    asm volatile("ld.acquire.gpu.global.b32 %0,[%1];" : "=r"(v) : "l"(p) : "memory");
    return v;
}
DEV_INLINE void st_rel(int* p, int v) {
    asm volatile("st.release.gpu.global.b32 [%0],%1;" :: "l"(p), "r"(v) : "memory");
}

DEV_INLINE float sigm(float x)   { return 1.0f / (1.0f + __expf(-x)); }
DEV_INLINE float tanh_f(float x) { float e = __expf(2.0f * x); return 1.0f - 2.0f / (e + 1.0f); }

// ------------- tf32 pre-rounding -------------
__global__ void round_all_k(const float* __restrict__ x,  const float* __restrict__ w0,
                            const float* __restrict__ w1, const float* __restrict__ wo) {
    const int N0 = 64 * 512 * 168;
    const int N1 = 2 * 2048 * 168;
    const int N2 = 2 * 2048 * 1024;
    const int N3 = 168 * 1024;
    int total = N0 + N1 + N2 + N3;
    for (int i = blockIdx.x * blockDim.x + threadIdx.x; i < total; i += gridDim.x * blockDim.x) {
        if (i < N0)                 g_xr[i] = tf32r(x[i]);
        else if (i < N0 + N1)       g_w0r[i - N0] = tf32r(w0[i - N0]);
        else if (i < N0 + N1 + N2)  g_w1r[i - N0 - N1] = tf32r(w1[i - N0 - N1]);
        else                        g_wor[i - N0 - N1 - N2] = tf32r(wo[i - N0 - N1 - N2]);
    }
}

__global__ void reset_k() {
    int gt = blockIdx.x * 256 + threadIdx.x;
    if (gt < 8 * 256) ((int*)g_bar)[gt] = 0;
    float* hb = &g_hbuf[0][0][0][0][0];
    for (int i = gt; i < 2 * 2 * 2 * 64 * 512; i += 64 * 256) hb[i] = 0.0f;
}

// ------------- tf32 GEMM, 4-stage cp.async pipeline -------------
// tile 128(M) x 64(N), k-tile 16, 256 threads (warps 4m x 2n, each m32 x n32)
// out offset = (m/DIV)*S1 + (m%DIV)*S2 + (n>>11)*S3 + (n&2047)
__global__ void __launch_bounds__(256, 2)
gemm_k(const float* __restrict__ A, const float* __restrict__ W,
       const float* __restrict__ bias, float* __restrict__ C,
       int M, int N, int K, int DIV, long long S1, long long S2, long long S3) {
    extern __shared__ float gsm[];
    float* Asm = gsm;                 // 4 x 128 x 20
    float* Bsm = gsm + 4 * 2560;      // 4 x  64 x 20

    int tid = threadIdx.x, lane = tid & 31, wid = tid >> 5;
    int wm = wid & 3, wn = wid >> 2;
    int mbase = blockIdx.y * 128, nbase = blockIdx.x * 64;
    int KT = (K + 15) >> 4;

    float acc[2][4][4];
#pragma unroll
    for (int mt = 0; mt < 2; mt++)
#pragma unroll
        for (int nt = 0; nt < 4; nt++)
#pragma unroll
            for (int e = 0; e < 4; e++) acc[mt][nt][e] = 0.0f;

    auto load_stage = [&](int kt) {
        int s = kt & 3;
        int k0 = kt * 16;
        float* as = Asm + s * 2560;
        float* bs = Bsm + s * 1280;
#pragma unroll
        for (int i = 0; i < 2; i++) {
            int ch = i * 256 + tid;
            int row = ch >> 2, seg = ch & 3;
            int k = k0 + seg * 4;
            int el = K - k; if (el > 4) el = 4; if (el < 0) el = 0;
            int bytes = el * 4;
            const float* src = A + (size_t)(mbase + row) * K + (bytes ? k : 0);
            cp16(&as[row * 20 + seg * 4], src, bytes);
        }
        {
            int row = tid >> 2, seg = tid & 3;
            int k = k0 + seg * 4;
            int n = nbase + row;
            int el = K - k; if (el > 4) el = 4; if (el < 0) el = 0;
            int bytes = el * 4;
            if (n >= N) bytes = 0;
            const float* src = (bytes ? (W + (size_t)n * K + k) : W);
            cp16(&bs[row * 20 + seg * 4], src, bytes);
        }
        cp_commit();
    };

    load_stage(0);
    if (KT > 1) load_stage(1);
    if (KT > 2) load_stage(2);

    for (int kt = 0; kt < KT; kt++) {
        cp_wait2();
        __syncthreads();
        if (kt + 3 < KT) load_stage(kt + 3);
        const float* as = Asm + (kt & 3) * 2560;
        const float* bs = Bsm + (kt & 3) * 1280;
#pragma unroll
        for (int k8 = 0; k8 < 2; k8++) {
            int kk = k8 * 8 + (lane & 3);
            unsigned a[2][4], b[4][2];
#pragma unroll
            for (int mt = 0; mt < 2; mt++) {
                int r0 = wm * 32 + mt * 16 + (lane >> 2);
                a[mt][0] = __float_as_uint(as[r0 * 20 + kk]);
                a[mt][1] = __float_as_uint(as[(r0 + 8) * 20 + kk]);
                a[mt][2] = __float_as_uint(as[r0 * 20 + kk + 4]);
                a[mt][3] = __float_as_uint(as[(r0 + 8) * 20 + kk + 4]);
            }
#pragma unroll
            for (int nt = 0; nt < 4; nt++) {
                int c0 = wn * 32 + nt * 8 + (lane >> 2);
                b[nt][0] = __float_as_uint(bs[c0 * 20 + kk]);
                b[nt][1] = __float_as_uint(bs[c0 * 20 + kk + 4]);
            }
#pragma unroll
            for (int mt = 0; mt < 2; mt++)
#pragma unroll
                for (int nt = 0; nt < 4; nt++)
                    mma8(acc[mt][nt], a[mt], b[nt]);
        }
    }

#pragma unroll
    for (int mt = 0; mt < 2; mt++) {
#pragma unroll
        for (int nt = 0; nt < 4; nt++) {
            int m0 = mbase + wm * 32 + mt * 16 + (lane >> 2);
            int n0 = nbase + wn * 32 + nt * 8 + 2 * (lane & 3);
            if (n0 < N) {
                float bv0 = bias[n0], bv1 = bias[n0 + 1];
                long long nb = (long long)(n0 >> 11) * S3 + (n0 & 2047);
                long long o0 = (long long)(m0 / DIV) * S1 + (long long)(m0 % DIV) * S2 + nb;
                int m1 = m0 + 8;
                long long o1 = (long long)(m1 / DIV) * S1 + (long long)(m1 % DIV) * S2 + nb;
                *(float2*)(C + o0) = make_float2(acc[mt][nt][0] + bv0, acc[mt][nt][1] + bv1);
                *(float2*)(C + o1) = make_float2(acc[mt][nt][2] + bv0, acc[mt][nt][3] + bv1);
            }
        }
    }
}

// ------------- persistent bidirectional LSTM recurrence, 2-D split (R7) -------------
// grid 128: d = bx>>6, bh = (bx>>5)&1, ncta = bx&31.
// CTA owns batches [bh*32, bh*32+32) x hidden units [ncta*16, ncta*16+16).
// Step protocol: Gs prefetch -> single warp-0 poll of 32 flags -> sync ->
// depth-3 chunk pipeline (8 chunks of k=64).
__global__ void __launch_bounds__(128, 1)
lstm_k(const float* __restrict__ Whh, const float* __restrict__ G,
       float* __restrict__ hout, int layer) {
    extern __shared__ float sm[];
    float* bf  = sm;                            // W frags [wn4][c8][k8 8][lane32][4] = 32768
    float* hs  = sm + 32768;                    // h: 4 bufs x (32 x 68) = 8704
    float* Gs  = sm + 32768 + 8704;             // 32 x 64 = 2048
    float* dmp = sm + 32768 + 8704 + 2048;      // 32 x 68 = 2176

    const int tid = threadIdx.x;
    const int lane = tid & 31, wn = tid >> 5;   // 4 n-warps
    const int d = blockIdx.x >> 6;
    const int bh = (blockIdx.x >> 5) & 1;
    const int ncta = blockIdx.x & 31;
    const int jbase = ncta * 16;
    int* bar = &g_bar[layer * 4 + d * 2 + bh][0];

    // ---- preload Whh slice (64 rows x 512) into fragment-ordered SMEM ----
    const float* Wd = Whh + (size_t)d * 2048 * 512;
    for (int idx = tid; idx < 64 * 512; idx += 128) {
        int ns = idx >> 9, k = idx & 511;
        int grow = (ns & 3) * 512 + jbase + (ns >> 2);   // gate*512 + unit
        float v = tf32r(Wd[(size_t)grow * 512 + k]);
        int wnn = ns >> 4;               // owning warp
        int r = ns & 15;                 // row within warp tile
        int nt = r >> 3;
        int c = k >> 6, k8 = (k >> 3) & 7;
        int ln = ((r & 7) << 2) | (k & 3);
        int elem = nt * 2 + ((k >> 2) & 1);
        bf[(((wnn * 8 + c) * 8 + k8) * 32 + ln) * 4 + elem] = v;
    }
    __syncthreads();

    const float* Gbase = G + (size_t)d * 512 * 64 * 2048;
    float cst[4];
#pragma unroll
    for (int i = 0; i < 4; i++) cst[i] = 0.0f;
    const int b_ep = tid >> 2;           // local batch 0..31
    const int uoff = (tid & 3) * 4;      // unit group 0,4,8,12

    for (int t = 0; t < 512; t++) {
        int tt = d ? (511 - t) : t;

        // stage gate preactivations (no dependency on other CTAs)
        const float* Gp = Gbase + (size_t)tt * 64 * 2048 + (size_t)(bh * 32) * 2048;
#pragma unroll
        for (int i = 0; i < 4; i++) {
            int s = tid * 4 + i;                  // 0..511
            int b = s >> 4, g = (s >> 2) & 3, part = s & 3;
            cp16(Gs + b * 64 + g * 16 + part * 4,
                 Gp + (size_t)b * 2048 + g * 512 + jbase + part * 4, 16);
        }
        cp_commit();

        // wait for the 32 CTAs of this (d, bh) chain to finish step t-1
        if (t > 0 && wn == 0) {
            for (;;) {
                int v = ld_acq(&bar[lane * 8]);
                if (__all_sync(0xffffffffu, v >= t)) break;
            }
        }
        __syncthreads();

        const float* hsrc = &g_hbuf[layer][d][(t + 1) & 1][bh * 32][0];

        // stage one 64-wide k-chunk of h for 32 batches (2048 floats, 4 cp16/thr)
        auto stage = [&](int c) {
            float* dst = hs + (c & 3) * 2176;
            const float* src = hsrc + c * 64;
#pragma unroll
            for (int i = 0; i < 4; i++) {
                int s = tid * 4 + i;              // 0..511
                int b = s >> 4, kp = (s & 15) * 4;
                cp16(dst + b * 68 + kp, src + b * 512 + kp, 16);
            }
            cp_commit();
        };
        stage(0);
        stage(1);
        stage(2);

        float acc[2][2][4];
#pragma unroll
        for (int mt = 0; mt < 2; mt++)
#pragma unroll
            for (int nt = 0; nt < 2; nt++)
#pragma unroll
                for (int e = 0; e < 4; e++) acc[mt][nt][e] = 0.0f;

#pragma unroll
        for (int c = 0; c < 8; c++) {
            if (c < 6) cp_wait2(); else cp_wait0();
            __syncthreads();
            if (c < 5) stage(c + 3);

            const float* hc = hs + (c & 3) * 2176;
            const float* Bb = bf + ((wn * 8 + c) * 8) * 128;
#pragma unroll
            for (int k8 = 0; k8 < 8; k8++) {
                int kk = k8 * 8 + (lane & 3);
                int r0 = lane >> 2;
                unsigned a[2][4], bb[2][2];
#pragma unroll
                for (int mt = 0; mt < 2; mt++) {
                    int r = r0 + mt * 16;
                    a[mt][0] = __float_as_uint(hc[r * 68 + kk]);
                    a[mt][1] = __float_as_uint(hc[(r + 8) * 68 + kk]);
                    a[mt][2] = __float_as_uint(hc[r * 68 + kk + 4]);
                    a[mt][3] = __float_as_uint(hc[(r + 8) * 68 + kk + 4]);
                }
                float4 bv = *(const float4*)(Bb + (k8 * 32 + lane) * 4);
                bb[0][0] = __float_as_uint(bv.x); bb[0][1] = __float_as_uint(bv.y);
                bb[1][0] = __float_as_uint(bv.z); bb[1][1] = __float_as_uint(bv.w);
#pragma unroll
                for (int mt = 0; mt < 2; mt++)
#pragma unroll
                    for (int nt = 0; nt < 2; nt++)
                        mma8(acc[mt][nt], a[mt], bb[nt]);
            }
        }

        // dump gates to SMEM for the cross-thread transpose (m 0..31, n 0..63)
#pragma unroll
        for (int mt = 0; mt < 2; mt++) {
#pragma unroll
            for (int nt = 0; nt < 2; nt++) {
                int m0 = mt * 16 + (lane >> 2);
                int n0 = wn * 16 + nt * 8 + 2 * (lane & 3);
                dmp[m0 * 68 + n0]           = acc[mt][nt][0];
                dmp[m0 * 68 + n0 + 1]       = acc[mt][nt][1];
                dmp[(m0 + 8) * 68 + n0]     = acc[mt][nt][2];
                dmp[(m0 + 8) * 68 + n0 + 1] = acc[mt][nt][3];
            }
        }
        __syncthreads();

        // epilogue: thread handles local batch b_ep, units uoff..uoff+3
        float hr[4];
#pragma unroll
        for (int i = 0; i < 4; i++) {
            int u = uoff + i;
            float gi = dmp[b_ep * 68 + u * 4 + 0] + Gs[b_ep * 64 + 0 * 16 + u];
            float gf = dmp[b_ep * 68 + u * 4 + 1] + Gs[b_ep * 64 + 1 * 16 + u];
            float gg = dmp[b_ep * 68 + u * 4 + 2] + Gs[b_ep * 64 + 2 * 16 + u];
            float go = dmp[b_ep * 68 + u * 4 + 3] + Gs[b_ep * 64 + 3 * 16 + u];
            float cv = sigm(gf) * cst[i] + sigm(gi) * tanh_f(gg);
            cst[i] = cv;
            hr[i] = tf32r(sigm(go) * tanh_f(cv));
        }

        int bglob = bh * 32 + b_ep;
        float* hb = &g_hbuf[layer][d][t & 1][bglob][jbase + uoff];
        *(float4*)hb = make_float4(hr[0], hr[1], hr[2], hr[3]);
        float* ho = hout + ((size_t)tt * 64 + bglob) * 1024 + d * 512 + jbase + uoff;
        *(float4*)ho = make_float4(hr[0], hr[1], hr[2], hr[3]);

        __syncthreads();   // Gs/dmp/hs WAR protection + order stores before release
        if (tid == 0 && t < 511) st_rel(&bar[ncta * 8], t + 1);
    }
}

// ------------- host launcher -------------
extern "C" void kernel_launch(void* const* d_in, const int* in_sizes, int n_in,
                              void* d_out, int out_size) {
    (void)in_sizes; (void)n_in; (void)out_size;
    const float* Whh0 = (const float*)d_in[2];
    const float* b0   = (const float*)d_in[3];
    const float* Whh1 = (const float*)d_in[5];
    const float* b1   = (const float*)d_in[6];
    const float* bout = (const float*)d_in[8];
    float* out = (float*)d_out;

    const int LSMEM = (32768 + 8704 + 2048 + 2176) * 4;   // 182784
    const int GSMEM = (4 * 2560 + 4 * 1280) * 4;          // 61440
    cudaFuncSetAttribute(lstm_k, cudaFuncAttributeMaxDynamicSharedMemorySize, LSMEM);
    cudaFuncSetAttribute(gemm_k, cudaFuncAttributeMaxDynamicSharedMemorySize, GSMEM);

    float *xr, *w0r, *w1r, *wor, *G, *h1, *h2;
    cudaGetSymbolAddress((void**)&xr,  g_xr);
    cudaGetSymbolAddress((void**)&w0r, g_w0r);
    cudaGetSymbolAddress((void**)&w1r, g_w1r);
    cudaGetSymbolAddress((void**)&wor, g_wor);
    cudaGetSymbolAddress((void**)&G,   g_G);
    cudaGetSymbolAddress((void**)&h1,  g_h1);
    cudaGetSymbolAddress((void**)&h2,  g_h2);

    const long long GSZ = 512LL * 64 * 2048;

    reset_k<<<64, 256>>>();
    round_all_k<<<2048, 256>>>((const float*)d_in[0], (const float*)d_in[1],
                               (const float*)d_in[4], (const float*)d_in[7]);

    // layer-0 input GEMM, both directions fused on N (N=4096, K=168)
    gemm_k<<<dim3(64, 256), 256, GSMEM>>>(xr, w0r, b0, G,
                                          32768, 4096, 168, 512, 2048LL, 131072LL, GSZ);
    lstm_k<<<128, 128, LSMEM>>>(Whh0, G, h1, 0);

    // layer-1 input GEMM (N=4096, K=1024)
    gemm_k<<<dim3(64, 256), 256, GSMEM>>>(h1, w1r, b1, G,
                                          32768, 4096, 1024, 64, 131072LL, 2048LL, GSZ);
    lstm_k<<<128, 128, LSMEM>>>(Whh1, G, h2, 1);

    // output projection
    gemm_k<<<dim3(3, 256), 256, GSMEM>>>(h2, wor, bout, out,
                                         32768, 168, 1024, 64, 168LL, 86016LL, 0LL);
}

// round 10
// speedup vs baseline: 1.6000x; 1.0783x over previous
#include <cuda_runtime.h>
#include <cstdint>

#define DEV_INLINE __device__ __forceinline__

// ------------- device-global scratch -------------
static __device__ float g_G[2ULL * 512 * 64 * 2048];    // gate preactivations [d][T][B][4H]
static __device__ float g_h1[512 * 64 * 1024];          // layer-0 output [T][B][2H]
static __device__ float g_h2[512 * 64 * 1024];          // layer-1 output
static __device__ float g_xr[64 * 512 * 168];           // tf32-rounded x
static __device__ float g_w0r[2 * 2048 * 168];
static __device__ float g_w1r[2 * 2048 * 1024];
static __device__ float g_wor[168 * 1024];
static __device__ float g_hbuf[2][2][2][64][512];       // [layer][dir][parity][b][k]
static __device__ int   g_bar[8][256];                  // [layer*4+d*2+bh][cta*8] flags

// ------------- helpers -------------
DEV_INLINE unsigned sptr(const void* p) { return (unsigned)__cvta_generic_to_shared(p); }

DEV_INLINE void cp16(void* d, const void* s, int bytes) {
    asm volatile("cp.async.cg.shared.global [%0],[%1],16,%2;\n"
                 :: "r"(sptr(d)), "l"(s), "r"(bytes));
}
DEV_INLINE void cp_commit() { asm volatile("cp.async.commit_group;\n"); }
DEV_INLINE void cp_wait0()  { asm volatile("cp.async.wait_group 0;\n"); }
DEV_INLINE void cp_wait2()  { asm volatile("cp.async.wait_group 2;\n"); }

DEV_INLINE float tf32r(float x) {
    unsigned r;
    asm("cvt.rna.tf32.f32 %0, %1;" : "=r"(r) : "f"(x));
    return __uint_as_float(r);
}

DEV_INLINE void mma8(float c[4], const unsigned a[4], const unsigned b[2]) {
    asm volatile("mma.sync.aligned.m16n8k8.row.col.f32.tf32.tf32.f32 "
                 "{%0,%1,%2,%3},{%4,%5,%6,%7},{%8,%9},{%0,%1,%2,%3};"
                 : "+f"(c[0]), "+f"(c[1]), "+f"(c[2]), "+f"(c[3])
                 : "r"(a[0]), "r"(a[1]), "r"(a[2]), "r"(a[3]),
                   "r"(b[0]), "r"(b[1]));
}

DEV_INLINE int ld_acq(const int* p) {
    int v;
    asm volatile("ld.acquire.gpu.global.b32 %0,[%1];" : "=r"(v) : "l"(p) : "memory");
    return v;
}
DEV_INLINE void st_rel(int* p, int v) {
    asm volatile("st.release.gpu.global.b32 [%0],%1;" :: "l"(p), "r"(v) : "memory");
}

DEV_INLINE float sigm(float x)   { return 1.0f / (1.0f + __expf(-x)); }
DEV_INLINE float tanh_f(float x) { float e = __expf(2.0f * x); return 1.0f - 2.0f / (e + 1.0f); }

// ------------- tf32 pre-rounding -------------
__global__ void round_all_k(const float* __restrict__ x,  const float* __restrict__ w0,
                            const float* __restrict__ w1, const float* __restrict__ wo) {
    const int N0 = 64 * 512 * 168;
    const int N1 = 2 * 2048 * 168;
    const int N2 = 2 * 2048 * 1024;
    const int N3 = 168 * 1024;
    int total = N0 + N1 + N2 + N3;
    for (int i = blockIdx.x * blockDim.x + threadIdx.x; i < total; i += gridDim.x * blockDim.x) {
        if (i < N0)                 g_xr[i] = tf32r(x[i]);
        else if (i < N0 + N1)       g_w0r[i - N0] = tf32r(w0[i - N0]);
        else if (i < N0 + N1 + N2)  g_w1r[i - N0 - N1] = tf32r(w1[i - N0 - N1]);
        else                        g_wor[i - N0 - N1 - N2] = tf32r(wo[i - N0 - N1 - N2]);
    }
}

__global__ void reset_k() {
    int gt = blockIdx.x * 256 + threadIdx.x;
    if (gt < 8 * 256) ((int*)g_bar)[gt] = 0;
    float* hb = &g_hbuf[0][0][0][0][0];
    for (int i = gt; i < 2 * 2 * 2 * 64 * 512; i += 64 * 256) hb[i] = 0.0f;
}

// ------------- tf32 GEMM, 4-stage cp.async pipeline -------------
// tile 128(M) x 64(N), k-tile 16, 256 threads (warps 4m x 2n, each m32 x n32)
// out offset = (m/DIV)*S1 + (m%DIV)*S2 + (n>>11)*S3 + (n&2047)
__global__ void __launch_bounds__(256, 2)
gemm_k(const float* __restrict__ A, const float* __restrict__ W,
       const float* __restrict__ bias, float* __restrict__ C,
       int M, int N, int K, int DIV, long long S1, long long S2, long long S3) {
    extern __shared__ float gsm[];
    float* Asm = gsm;                 // 4 x 128 x 20
    float* Bsm = gsm + 4 * 2560;      // 4 x  64 x 20

    int tid = threadIdx.x, lane = tid & 31, wid = tid >> 5;
    int wm = wid & 3, wn = wid >> 2;
    int mbase = blockIdx.y * 128, nbase = blockIdx.x * 64;
    int KT = (K + 15) >> 4;

    float acc[2][4][4];
#pragma unroll
    for (int mt = 0; mt < 2; mt++)
#pragma unroll
        for (int nt = 0; nt < 4; nt++)
#pragma unroll
            for (int e = 0; e < 4; e++) acc[mt][nt][e] = 0.0f;

    auto load_stage = [&](int kt) {
        int s = kt & 3;
        int k0 = kt * 16;
        float* as = Asm + s * 2560;
        float* bs = Bsm + s * 1280;
#pragma unroll
        for (int i = 0; i < 2; i++) {
            int ch = i * 256 + tid;
            int row = ch >> 2, seg = ch & 3;
            int k = k0 + seg * 4;
            int el = K - k; if (el > 4) el = 4; if (el < 0) el = 0;
            int bytes = el * 4;
            const float* src = A + (size_t)(mbase + row) * K + (bytes ? k : 0);
            cp16(&as[row * 20 + seg * 4], src, bytes);
        }
        {
            int row = tid >> 2, seg = tid & 3;
            int k = k0 + seg * 4;
            int n = nbase + row;
            int el = K - k; if (el > 4) el = 4; if (el < 0) el = 0;
            int bytes = el * 4;
            if (n >= N) bytes = 0;
            const float* src = (bytes ? (W + (size_t)n * K + k) : W);
            cp16(&bs[row * 20 + seg * 4], src, bytes);
        }
        cp_commit();
    };

    load_stage(0);
    if (KT > 1) load_stage(1);
    if (KT > 2) load_stage(2);

    for (int kt = 0; kt < KT; kt++) {
        cp_wait2();
        __syncthreads();
        if (kt + 3 < KT) load_stage(kt + 3);
        const float* as = Asm + (kt & 3) * 2560;
        const float* bs = Bsm + (kt & 3) * 1280;
#pragma unroll
        for (int k8 = 0; k8 < 2; k8++) {
            int kk = k8 * 8 + (lane & 3);
            unsigned a[2][4], b[4][2];
#pragma unroll
            for (int mt = 0; mt < 2; mt++) {
                int r0 = wm * 32 + mt * 16 + (lane >> 2);
                a[mt][0] = __float_as_uint(as[r0 * 20 + kk]);
                a[mt][1] = __float_as_uint(as[(r0 + 8) * 20 + kk]);
                a[mt][2] = __float_as_uint(as[r0 * 20 + kk + 4]);
                a[mt][3] = __float_as_uint(as[(r0 + 8) * 20 + kk + 4]);
            }
#pragma unroll
            for (int nt = 0; nt < 4; nt++) {
                int c0 = wn * 32 + nt * 8 + (lane >> 2);
                b[nt][0] = __float_as_uint(bs[c0 * 20 + kk]);
                b[nt][1] = __float_as_uint(bs[c0 * 20 + kk + 4]);
            }
#pragma unroll
            for (int mt = 0; mt < 2; mt++)
#pragma unroll
                for (int nt = 0; nt < 4; nt++)
                    mma8(acc[mt][nt], a[mt], b[nt]);
        }
    }

#pragma unroll
    for (int mt = 0; mt < 2; mt++) {
#pragma unroll
        for (int nt = 0; nt < 4; nt++) {
            int m0 = mbase + wm * 32 + mt * 16 + (lane >> 2);
            int n0 = nbase + wn * 32 + nt * 8 + 2 * (lane & 3);
            if (n0 < N) {
                float bv0 = bias[n0], bv1 = bias[n0 + 1];
                long long nb = (long long)(n0 >> 11) * S3 + (n0 & 2047);
                long long o0 = (long long)(m0 / DIV) * S1 + (long long)(m0 % DIV) * S2 + nb;
                int m1 = m0 + 8;
                long long o1 = (long long)(m1 / DIV) * S1 + (long long)(m1 % DIV) * S2 + nb;
                *(float2*)(C + o0) = make_float2(acc[mt][nt][0] + bv0, acc[mt][nt][1] + bv1);
                *(float2*)(C + o1) = make_float2(acc[mt][nt][2] + bv0, acc[mt][nt][3] + bv1);
            }
        }
    }
}

// ------------- persistent bidirectional LSTM recurrence, 2-D split, 8 warps ----
// grid 128: d = bx>>6, bh = (bx>>5)&1, ncta = bx&31.
// CTA owns batches [bh*32, bh*32+32) x hidden units [ncta*16, ncta*16+16).
// 256 threads = 8 warps (wm2 x wn4), warp tile m16 x n16, k512.
// 2 warps/SMSP for latency hiding. Arithmetic identical to the 128-thread
// version (old mt index -> wm warp index), so rel_err must match exactly.
__global__ void __launch_bounds__(256, 1)
lstm_k(const float* __restrict__ Whh, const float* __restrict__ G,
       float* __restrict__ hout, int layer) {
    extern __shared__ float sm[];
    float* bf  = sm;                            // W frags [wn4][c8][k8 8][lane32][4] = 32768
    float* hs  = sm + 32768;                    // h: 4 bufs x (32 x 68) = 8704
    float* Gs  = sm + 32768 + 8704;             // 32 x 64 = 2048
    float* dmp = sm + 32768 + 8704 + 2048;      // 32 x 68 = 2176

    const int tid = threadIdx.x;
    const int lane = tid & 31, wid = tid >> 5;
    const int wm = wid & 1;                     // m-half: batches 0-15 / 16-31
    const int wn = wid >> 1;                    // 0..3 n-warps
    const int d = blockIdx.x >> 6;
    const int bh = (blockIdx.x >> 5) & 1;
    const int ncta = blockIdx.x & 31;
    const int jbase = ncta * 16;
    int* bar = &g_bar[layer * 4 + d * 2 + bh][0];

    // ---- preload Whh slice (64 rows x 512) into fragment-ordered SMEM ----
    const float* Wd = Whh + (size_t)d * 2048 * 512;
    for (int idx = tid; idx < 64 * 512; idx += 256) {
        int ns = idx >> 9, k = idx & 511;
        int grow = (ns & 3) * 512 + jbase + (ns >> 2);   // gate*512 + unit
        float v = tf32r(Wd[(size_t)grow * 512 + k]);
        int wnn = ns >> 4;               // owning n-warp
        int r = ns & 15;                 // row within warp tile
        int nt = r >> 3;
        int c = k >> 6, k8 = (k >> 3) & 7;
        int ln = ((r & 7) << 2) | (k & 3);
        int elem = nt * 2 + ((k >> 2) & 1);
        bf[(((wnn * 8 + c) * 8 + k8) * 32 + ln) * 4 + elem] = v;
    }
    __syncthreads();

    const float* Gbase = G + (size_t)d * 512 * 64 * 2048;
    float cst[2];
    cst[0] = 0.0f; cst[1] = 0.0f;
    const int b_ep = tid >> 3;           // local batch 0..31
    const int uoff = (tid & 7) * 2;      // unit pair 0,2,...,14

    for (int t = 0; t < 512; t++) {
        int tt = d ? (511 - t) : t;

        // stage gate preactivations (no dependency on other CTAs)
        const float* Gp = Gbase + (size_t)tt * 64 * 2048 + (size_t)(bh * 32) * 2048;
#pragma unroll
        for (int i = 0; i < 2; i++) {
            int s = tid * 2 + i;                  // 0..511
            int b = s >> 4, g = (s >> 2) & 3, part = s & 3;
            cp16(Gs + b * 64 + g * 16 + part * 4,
                 Gp + (size_t)b * 2048 + g * 512 + jbase + part * 4, 16);
        }
        cp_commit();

        // wait for the 32 CTAs of this (d, bh) chain to finish step t-1
        if (t > 0 && wid == 0) {
            for (;;) {
                int v = ld_acq(&bar[lane * 8]);
                if (__all_sync(0xffffffffu, v >= t)) break;
            }
        }
        __syncthreads();

        const float* hsrc = &g_hbuf[layer][d][(t + 1) & 1][bh * 32][0];

        // stage one 64-wide k-chunk of h for 32 batches (2048 floats, 2 cp16/thr)
        auto stage = [&](int c) {
            float* dst = hs + (c & 3) * 2176;
            const float* src = hsrc + c * 64;
#pragma unroll
            for (int i = 0; i < 2; i++) {
                int s = tid * 2 + i;              // 0..511
                int b = s >> 4, kp = (s & 15) * 4;
                cp16(dst + b * 68 + kp, src + b * 512 + kp, 16);
            }
            cp_commit();
        };
        stage(0);
        stage(1);
        stage(2);

        float acc[2][4];
#pragma unroll
        for (int nt = 0; nt < 2; nt++)
#pragma unroll
            for (int e = 0; e < 4; e++) acc[nt][e] = 0.0f;

#pragma unroll
        for (int c = 0; c < 8; c++) {
            if (c < 6) cp_wait2(); else cp_wait0();
            __syncthreads();
            if (c < 5) stage(c + 3);

            const float* hc = hs + (c & 3) * 2176;
            const float* Bb = bf + ((wn * 8 + c) * 8) * 128;
#pragma unroll
            for (int k8 = 0; k8 < 8; k8++) {
                int kk = k8 * 8 + (lane & 3);
                int r = wm * 16 + (lane >> 2);
                unsigned a[4], bb[2][2];
                a[0] = __float_as_uint(hc[r * 68 + kk]);
                a[1] = __float_as_uint(hc[(r + 8) * 68 + kk]);
                a[2] = __float_as_uint(hc[r * 68 + kk + 4]);
                a[3] = __float_as_uint(hc[(r + 8) * 68 + kk + 4]);
                float4 bv = *(const float4*)(Bb + (k8 * 32 + lane) * 4);
                bb[0][0] = __float_as_uint(bv.x); bb[0][1] = __float_as_uint(bv.y);
                bb[1][0] = __float_as_uint(bv.z); bb[1][1] = __float_as_uint(bv.w);
#pragma unroll
                for (int nt = 0; nt < 2; nt++)
                    mma8(acc[nt], a, bb[nt]);
            }
        }

        // dump gates to SMEM for the cross-thread transpose (m 0..31, n 0..63)
#pragma unroll
        for (int nt = 0; nt < 2; nt++) {
            int m0 = wm * 16 + (lane >> 2);
            int n0 = wn * 16 + nt * 8 + 2 * (lane & 3);
            dmp[m0 * 68 + n0]           = acc[nt][0];
            dmp[m0 * 68 + n0 + 1]       = acc[nt][1];
            dmp[(m0 + 8) * 68 + n0]     = acc[nt][2];
            dmp[(m0 + 8) * 68 + n0 + 1] = acc[nt][3];
        }
        __syncthreads();

        // epilogue: thread handles local batch b_ep, units uoff, uoff+1
        float hr[2];
#pragma unroll
        for (int i = 0; i < 2; i++) {
            int u = uoff + i;
            float gi = dmp[b_ep * 68 + u * 4 + 0] + Gs[b_ep * 64 + 0 * 16 + u];
            float gf = dmp[b_ep * 68 + u * 4 + 1] + Gs[b_ep * 64 + 1 * 16 + u];
            float gg = dmp[b_ep * 68 + u * 4 + 2] + Gs[b_ep * 64 + 2 * 16 + u];
            float go = dmp[b_ep * 68 + u * 4 + 3] + Gs[b_ep * 64 + 3 * 16 + u];
            float cv = sigm(gf) * cst[i] + sigm(gi) * tanh_f(gg);
            cst[i] = cv;
            hr[i] = tf32r(sigm(go) * tanh_f(cv));
        }

        int bglob = bh * 32 + b_ep;
        float* hb = &g_hbuf[layer][d][t & 1][bglob][jbase + uoff];
        *(float2*)hb = make_float2(hr[0], hr[1]);
        float* ho = hout + ((size_t)tt * 64 + bglob) * 1024 + d * 512 + jbase + uoff;
        *(float2*)ho = make_float2(hr[0], hr[1]);

        __syncthreads();   // Gs/dmp/hs WAR protection + order stores before release
        if (tid == 0 && t < 511) st_rel(&bar[ncta * 8], t + 1);
    }
}

// ------------- host launcher -------------
extern "C" void kernel_launch(void* const* d_in, const int* in_sizes, int n_in,
                              void* d_out, int out_size) {
    (void)in_sizes; (void)n_in; (void)out_size;
    const float* Whh0 = (const float*)d_in[2];
    const float* b0   = (const float*)d_in[3];
    const float* Whh1 = (const float*)d_in[5];
    const float* b1   = (const float*)d_in[6];
    const float* bout = (const float*)d_in[8];
    float* out = (float*)d_out;

    const int LSMEM = (32768 + 8704 + 2048 + 2176) * 4;   // 182784
    const int GSMEM = (4 * 2560 + 4 * 1280) * 4;          // 61440
    cudaFuncSetAttribute(lstm_k, cudaFuncAttributeMaxDynamicSharedMemorySize, LSMEM);
    cudaFuncSetAttribute(gemm_k, cudaFuncAttributeMaxDynamicSharedMemorySize, GSMEM);

    float *xr, *w0r, *w1r, *wor, *G, *h1, *h2;
    cudaGetSymbolAddress((void**)&xr,  g_xr);
    cudaGetSymbolAddress((void**)&w0r, g_w0r);
    cudaGetSymbolAddress((void**)&w1r, g_w1r);
    cudaGetSymbolAddress((void**)&wor, g_wor);
    cudaGetSymbolAddress((void**)&G,   g_G);
    cudaGetSymbolAddress((void**)&h1,  g_h1);
    cudaGetSymbolAddress((void**)&h2,  g_h2);

    const long long GSZ = 512LL * 64 * 2048;

    reset_k<<<64, 256>>>();
    round_all_k<<<2048, 256>>>((const float*)d_in[0], (const float*)d_in[1],
                               (const float*)d_in[4], (const float*)d_in[7]);

    // layer-0 input GEMM, both directions fused on N (N=4096, K=168)
    gemm_k<<<dim3(64, 256), 256, GSMEM>>>(xr, w0r, b0, G,
                                          32768, 4096, 168, 512, 2048LL, 131072LL, GSZ);
    lstm_k<<<128, 256, LSMEM>>>(Whh0, G, h1, 0);

    // layer-1 input GEMM (N=4096, K=1024)
    gemm_k<<<dim3(64, 256), 256, GSMEM>>>(h1, w1r, b1, G,
                                          32768, 4096, 1024, 64, 131072LL, 2048LL, GSZ);
    lstm_k<<<128, 256, LSMEM>>>(Whh1, G, h2, 1);

    // output projection
    gemm_k<<<dim3(3, 256), 256, GSMEM>>>(h2, wor, bout, out,
                                         32768, 168, 1024, 64, 168LL, 86016LL, 0LL);
}